// round 6
// baseline (speedup 1.0000x reference)
#include <cuda_runtime.h>

#define NN 1024
#define HH 128
#define NJB 16          // j-blocks of 64

// Device-global scratch (no allocation allowed)
__device__ float g_part[NJB * NN * HH];   // per-jblock partial aggregates (8 MB)
__device__ float g_gi[NN * 3 * HH];       // gi = agg @ w_ih^T   [1024][384]
__device__ float g_gh[NN * 3 * HH];       // gh = nf  @ w_hh^T   [1024][384]

// ---------------------------------------------------------------------------
// Kernel 1: partial aggregation over a 64-j block, smem-staged nf tile.
// grid (128 iblocks, 16 jblocks), block 256 (8 warps; warp w owns i=ib*8+w).
// smem ~33KB -> 6 CTAs/SM -> 48 warps (75% occ) to keep DRAM queues full.
// Warp-local ballot-scan compaction; 4-deep gated __ldcs pipeline.
// ---------------------------------------------------------------------------
__global__ __launch_bounds__(256) void agg_kernel(
    const float* __restrict__ nf,
    const int*   __restrict__ adj,
    const float* __restrict__ T)
{
    const int ib   = blockIdx.x;
    const int jb   = blockIdx.y;
    const int tid  = threadIdx.x;
    const int lane = tid & 31;
    const int w    = tid >> 5;
    const int i    = ib * 8 + w;

    __shared__ float4 snf[64][32];             // 32 KB nf tile
    __shared__ unsigned char slist[8][64];     // per-warp active-j list (rel)

    // Stage nf tile (coalesced)
    const float4* nf4 = (const float4*)nf;
    #pragma unroll
    for (int e = tid; e < 64 * 32; e += 256) {
        int r = e >> 5, c = e & 31;
        snf[r][c] = nf4[(jb * 64 + r) * 32 + c];
    }

    // Warp-local compaction: 2 adjacency ints per lane (64 j per warp)
    const int2 a = ((const int2*)adj)[(size_t)i * 512 + jb * 32 + lane];
    const int f0 = (a.x != 0), f1 = (a.y != 0);
    const int cnt = f0 + f1;
    int pre = cnt;
    #pragma unroll
    for (int d = 1; d < 32; d <<= 1) {
        int v = __shfl_up_sync(0xffffffffu, pre, d);
        if (lane >= d) pre += v;
    }
    const int total = __shfl_sync(0xffffffffu, pre, 31);
    pre -= cnt;
    {
        unsigned char* lst = slist[w];
        int p = pre, j0 = lane * 2;
        if (f0) lst[p++] = (unsigned char)(j0);
        if (f1) lst[p++] = (unsigned char)(j0 + 1);
    }
    __syncthreads();

    const float4* T4 = (const float4*)T;
    const size_t rowbase = (size_t)i * NN + jb * 64;
    const unsigned char* lst = slist[w];

    float4 a0 = make_float4(0.f,0.f,0.f,0.f);
    float4 a1 = make_float4(0.f,0.f,0.f,0.f);
    float4 a2 = make_float4(0.f,0.f,0.f,0.f);
    float4 a3 = make_float4(0.f,0.f,0.f,0.f);

    int e = 0;
    for (; e + 3 < total; e += 4) {
        const int j0 = lst[e], j1 = lst[e+1], j2 = lst[e+2], j3 = lst[e+3];
        float4 t0 = __ldcs(&T4[(rowbase + j0) * 32 + lane]);
        float4 t1 = __ldcs(&T4[(rowbase + j1) * 32 + lane]);
        float4 t2 = __ldcs(&T4[(rowbase + j2) * 32 + lane]);
        float4 t3 = __ldcs(&T4[(rowbase + j3) * 32 + lane]);
        float4 v0 = snf[j0][lane];
        float4 v1 = snf[j1][lane];
        float4 v2 = snf[j2][lane];
        float4 v3 = snf[j3][lane];
        a0.x += v0.x*t0.x; a0.y += v0.y*t0.y; a0.z += v0.z*t0.z; a0.w += v0.w*t0.w;
        a1.x += v1.x*t1.x; a1.y += v1.y*t1.y; a1.z += v1.z*t1.z; a1.w += v1.w*t1.w;
        a2.x += v2.x*t2.x; a2.y += v2.y*t2.y; a2.z += v2.z*t2.z; a2.w += v2.w*t2.w;
        a3.x += v3.x*t3.x; a3.y += v3.y*t3.y; a3.z += v3.z*t3.z; a3.w += v3.w*t3.w;
    }
    for (; e < total; e++) {
        const int j = lst[e];
        float4 t = __ldcs(&T4[(rowbase + j) * 32 + lane]);
        float4 f = snf[j][lane];
        a0.x += f.x*t.x; a0.y += f.y*t.y; a0.z += f.z*t.z; a0.w += f.w*t.w;
    }

    a0.x += a1.x + a2.x + a3.x;
    a0.y += a1.y + a2.y + a3.y;
    a0.z += a1.z + a2.z + a3.z;
    a0.w += a1.w + a2.w + a3.w;

    ((float4*)g_part)[((size_t)jb * NN + i) * 32 + lane] = a0;
}

// ---------------------------------------------------------------------------
// Kernel 2: tiled GEMM  C[1024 x 384] = A[1024 x 128] @ W[384 x 128]^T.
// grid (16 mtiles, 6 ntiles, 2): z=0 -> A=sum(g_part), W=wih, C=g_gi
//                                z=1 -> A=nf,          W=whh, C=g_gh
// B staged directly from row-major W (no transpose): sB[n][k4].
// Inner product: c[r][c] += dot4(a_r, b_c). 16 accumulators/thread.
// ---------------------------------------------------------------------------
__global__ __launch_bounds__(256) void gemm_kernel(
    const float* __restrict__ nf,
    const float* __restrict__ wih,
    const float* __restrict__ whh)
{
    const int mt  = blockIdx.x;
    const int nt  = blockIdx.y;
    const int zz  = blockIdx.z;
    const int tid = threadIdx.x;
    const int tx  = tid & 15;
    const int ty  = tid >> 4;

    const float4* A4 = (const float4*)nf;
    const float4* P4 = (const float4*)g_part;
    const float4* W4 = (const float4*)(zz ? whh : wih);
    float4*       C4 = (float4*)(zz ? g_gh : g_gi);

    __shared__ float4 sA[64][17];
    __shared__ float4 sB[64][17];

    const int mbase = mt * 64;
    const int nbase = nt * 64;

    float c00=0,c01=0,c02=0,c03=0, c10=0,c11=0,c12=0,c13=0;
    float c20=0,c21=0,c22=0,c23=0, c30=0,c31=0,c32=0,c33=0;

    #pragma unroll
    for (int kb = 0; kb < 2; kb++) {
        #pragma unroll
        for (int e = tid; e < 64 * 16; e += 256) {
            const int m = e >> 4, kq = e & 15;
            const size_t gidx = (size_t)(mbase + m) * 32 + kb * 16 + kq;
            float4 s;
            if (zz) {
                s = A4[gidx];
            } else {
                s = P4[gidx];
                #pragma unroll
                for (int p = 1; p < NJB; p++) {
                    float4 v = P4[(size_t)p * (NN * 32) + gidx];
                    s.x += v.x; s.y += v.y; s.z += v.z; s.w += v.w;
                }
            }
            sA[m][kq] = s;
        }
        #pragma unroll
        for (int e = tid; e < 64 * 16; e += 256) {
            const int n = e >> 4, kq = e & 15;
            sB[n][kq] = W4[(size_t)(nbase + n) * 32 + kb * 16 + kq];
        }
        __syncthreads();

        #pragma unroll
        for (int kq = 0; kq < 16; kq++) {
            const float4 a0 = sA[ty * 4 + 0][kq];
            const float4 a1 = sA[ty * 4 + 1][kq];
            const float4 a2 = sA[ty * 4 + 2][kq];
            const float4 a3 = sA[ty * 4 + 3][kq];
            const float4 b0 = sB[tx * 4 + 0][kq];
            const float4 b1 = sB[tx * 4 + 1][kq];
            const float4 b2 = sB[tx * 4 + 2][kq];
            const float4 b3 = sB[tx * 4 + 3][kq];

            c00 += a0.x*b0.x + a0.y*b0.y + a0.z*b0.z + a0.w*b0.w;
            c01 += a0.x*b1.x + a0.y*b1.y + a0.z*b1.z + a0.w*b1.w;
            c02 += a0.x*b2.x + a0.y*b2.y + a0.z*b2.z + a0.w*b2.w;
            c03 += a0.x*b3.x + a0.y*b3.y + a0.z*b3.z + a0.w*b3.w;
            c10 += a1.x*b0.x + a1.y*b0.y + a1.z*b0.z + a1.w*b0.w;
            c11 += a1.x*b1.x + a1.y*b1.y + a1.z*b1.z + a1.w*b1.w;
            c12 += a1.x*b2.x + a1.y*b2.y + a1.z*b2.z + a1.w*b2.w;
            c13 += a1.x*b3.x + a1.y*b3.y + a1.z*b3.z + a1.w*b3.w;
            c20 += a2.x*b0.x + a2.y*b0.y + a2.z*b0.z + a2.w*b0.w;
            c21 += a2.x*b1.x + a2.y*b1.y + a2.z*b1.z + a2.w*b1.w;
            c22 += a2.x*b2.x + a2.y*b2.y + a2.z*b2.z + a2.w*b2.w;
            c23 += a2.x*b3.x + a2.y*b3.y + a2.z*b3.z + a2.w*b3.w;
            c30 += a3.x*b0.x + a3.y*b0.y + a3.z*b0.z + a3.w*b0.w;
            c31 += a3.x*b1.x + a3.y*b1.y + a3.z*b1.z + a3.w*b1.w;
            c32 += a3.x*b2.x + a3.y*b2.y + a3.z*b2.z + a3.w*b2.w;
            c33 += a3.x*b3.x + a3.y*b3.y + a3.z*b3.z + a3.w*b3.w;
        }
        __syncthreads();
    }

    const int m0 = mbase + ty * 4;
    const int n4 = nt * 16 + tx;
    C4[(size_t)(m0 + 0) * 96 + n4] = make_float4(c00, c01, c02, c03);
    C4[(size_t)(m0 + 1) * 96 + n4] = make_float4(c10, c11, c12, c13);
    C4[(size_t)(m0 + 2) * 96 + n4] = make_float4(c20, c21, c22, c23);
    C4[(size_t)(m0 + 3) * 96 + n4] = make_float4(c30, c31, c32, c33);
}

// ---------------------------------------------------------------------------
// Kernel 3: fused GRU epilogue. One thread per (i,h).
// ---------------------------------------------------------------------------
__global__ __launch_bounds__(256) void gru_ep_kernel(
    const float* __restrict__ nf,
    const float* __restrict__ bih,
    const float* __restrict__ bhh,
    float*       __restrict__ out)
{
    const int idx = blockIdx.x * 256 + threadIdx.x;   // i*128 + h
    const int i = idx >> 7;
    const int h = idx & 127;
    const size_t base = (size_t)i * 384 + h;

    const float r = 1.f / (1.f + __expf(-(g_gi[base] + g_gh[base]
                                          + bih[h] + bhh[h])));
    const float z = 1.f / (1.f + __expf(-(g_gi[base + 128] + g_gh[base + 128]
                                          + bih[h + 128] + bhh[h + 128])));
    const float n = tanhf(g_gi[base + 256] + bih[h + 256]
                          + r * (g_gh[base + 256] + bhh[h + 256]));
    out[idx] = (1.f - z) * n + z * nf[idx];
}

extern "C" void kernel_launch(void* const* d_in, const int* in_sizes, int n_in,
                              void* d_out, int out_size)
{
    const float* nf  = (const float*)d_in[0];
    const int*   adj = (const int*)  d_in[1];
    const float* T   = (const float*)d_in[2];
    const float* wih = (const float*)d_in[3];
    const float* whh = (const float*)d_in[4];
    const float* bih = (const float*)d_in[5];
    const float* bhh = (const float*)d_in[6];
    float* out = (float*)d_out;

    agg_kernel<<<dim3(NN / 8, NJB), 256>>>(nf, adj, T);
    gemm_kernel<<<dim3(16, 6, 2), 256>>>(nf, wih, whh);
    gru_ep_kernel<<<(NN * HH) / 256, 256>>>(nf, bih, bhh, out);
}

// round 7
// speedup vs baseline: 1.0769x; 1.0769x over previous
#include <cuda_runtime.h>

#define NN 1024
#define HH 128
#define NJB 8           // partial slabs (each covers 128 j as 4 subtiles of 32)

// Device-global scratch (no allocation allowed)
__device__ float g_part[NJB * NN * HH];   // per-jblock partial aggregates
__device__ float g_gi[NN * 3 * HH];       // gi = agg @ w_ih^T   [1024][384]
__device__ float g_gh[NN * 3 * HH];       // gh = nf  @ w_hh^T   [1024][384]

// ---------------------------------------------------------------------------
// Kernel 1: partial aggregation. grid (128, 8) = 1024 CTAs -> ONE wave at
// 8 CTAs/SM (smem ~17 KB, warp-capped). Each CTA covers 128 j as 4 subtiles
// of 32 rows; warp w owns row i = ib*8+w. Ballot compaction; 4-deep gated
// __ldcs pipeline on T rows.
// ---------------------------------------------------------------------------
__global__ __launch_bounds__(256) void agg_kernel(
    const float* __restrict__ nf,
    const int*   __restrict__ adj,
    const float* __restrict__ T)
{
    const int ib   = blockIdx.x;
    const int jb   = blockIdx.y;
    const int tid  = threadIdx.x;
    const int lane = tid & 31;
    const int w    = tid >> 5;
    const int i    = ib * 8 + w;

    __shared__ float4 snf[32][32];             // 16 KB nf subtile
    __shared__ unsigned char slist[8][32];     // per-warp active-j list

    const float4* nf4 = (const float4*)nf;
    const float4* T4  = (const float4*)T;

    float4 a0 = make_float4(0.f,0.f,0.f,0.f);
    float4 a1 = make_float4(0.f,0.f,0.f,0.f);
    float4 a2 = make_float4(0.f,0.f,0.f,0.f);
    float4 a3 = make_float4(0.f,0.f,0.f,0.f);

    #pragma unroll 1
    for (int t = 0; t < 4; t++) {
        const int j0g = jb * 128 + t * 32;     // global j base of subtile

        __syncthreads();                       // previous subtile fully consumed
        // Stage nf subtile (coalesced; 4 float4 per thread)
        #pragma unroll
        for (int e = tid; e < 32 * 32; e += 256) {
            const int r = e >> 5, c = e & 31;
            snf[r][c] = nf4[(j0g + r) * 32 + c];
        }
        // Ballot compaction: 1 adjacency entry per lane
        const int av = adj[(size_t)i * NN + j0g + lane];
        const unsigned mask = __ballot_sync(0xffffffffu, av != 0);
        const int tot = __popc(mask);
        const int pre = __popc(mask & ((1u << lane) - 1u));
        if (av) slist[w][pre] = (unsigned char)lane;
        __syncthreads();                       // snf + slist ready

        const size_t rowbase = (size_t)i * NN + j0g;
        const unsigned char* lst = slist[w];

        int e = 0;
        for (; e + 3 < tot; e += 4) {
            const int j0 = lst[e], j1 = lst[e+1], j2 = lst[e+2], j3 = lst[e+3];
            float4 t0 = __ldcs(&T4[(rowbase + j0) * 32 + lane]);
            float4 t1 = __ldcs(&T4[(rowbase + j1) * 32 + lane]);
            float4 t2 = __ldcs(&T4[(rowbase + j2) * 32 + lane]);
            float4 t3 = __ldcs(&T4[(rowbase + j3) * 32 + lane]);
            float4 v0 = snf[j0][lane];
            float4 v1 = snf[j1][lane];
            float4 v2 = snf[j2][lane];
            float4 v3 = snf[j3][lane];
            a0.x += v0.x*t0.x; a0.y += v0.y*t0.y; a0.z += v0.z*t0.z; a0.w += v0.w*t0.w;
            a1.x += v1.x*t1.x; a1.y += v1.y*t1.y; a1.z += v1.z*t1.z; a1.w += v1.w*t1.w;
            a2.x += v2.x*t2.x; a2.y += v2.y*t2.y; a2.z += v2.z*t2.z; a2.w += v2.w*t2.w;
            a3.x += v3.x*t3.x; a3.y += v3.y*t3.y; a3.z += v3.z*t3.z; a3.w += v3.w*t3.w;
        }
        for (; e < tot; e++) {
            const int j = lst[e];
            float4 tv = __ldcs(&T4[(rowbase + j) * 32 + lane]);
            float4 fv = snf[j][lane];
            a0.x += fv.x*tv.x; a0.y += fv.y*tv.y; a0.z += fv.z*tv.z; a0.w += fv.w*tv.w;
        }
    }

    a0.x += a1.x + a2.x + a3.x;
    a0.y += a1.y + a2.y + a3.y;
    a0.z += a1.z + a2.z + a3.z;
    a0.w += a1.w + a2.w + a3.w;

    ((float4*)g_part)[((size_t)jb * NN + i) * 32 + lane] = a0;
}

// ---------------------------------------------------------------------------
// Kernel 2: tiled GEMM  C[1024 x 384] = A[1024 x 128] @ W[384 x 128]^T.
// grid (16 mtiles, 6 ntiles, 2): z=0 -> A=sum(g_part), W=wih, C=g_gi
//                                z=1 -> A=nf,          W=whh, C=g_gh
// B staged directly from row-major W; inner product c += dot4(a_r, b_c).
// ---------------------------------------------------------------------------
__global__ __launch_bounds__(256) void gemm_kernel(
    const float* __restrict__ nf,
    const float* __restrict__ wih,
    const float* __restrict__ whh)
{
    const int mt  = blockIdx.x;
    const int nt  = blockIdx.y;
    const int zz  = blockIdx.z;
    const int tid = threadIdx.x;
    const int tx  = tid & 15;
    const int ty  = tid >> 4;

    const float4* A4 = (const float4*)nf;
    const float4* P4 = (const float4*)g_part;
    const float4* W4 = (const float4*)(zz ? whh : wih);
    float4*       C4 = (float4*)(zz ? g_gh : g_gi);

    __shared__ float4 sA[64][17];
    __shared__ float4 sB[64][17];

    const int mbase = mt * 64;
    const int nbase = nt * 64;

    float c00=0,c01=0,c02=0,c03=0, c10=0,c11=0,c12=0,c13=0;
    float c20=0,c21=0,c22=0,c23=0, c30=0,c31=0,c32=0,c33=0;

    #pragma unroll
    for (int kb = 0; kb < 2; kb++) {
        #pragma unroll
        for (int e = tid; e < 64 * 16; e += 256) {
            const int m = e >> 4, kq = e & 15;
            const size_t gidx = (size_t)(mbase + m) * 32 + kb * 16 + kq;
            float4 s;
            if (zz) {
                s = A4[gidx];
            } else {
                s = P4[gidx];
                #pragma unroll
                for (int p = 1; p < NJB; p++) {
                    float4 v = P4[(size_t)p * (NN * 32) + gidx];
                    s.x += v.x; s.y += v.y; s.z += v.z; s.w += v.w;
                }
            }
            sA[m][kq] = s;
        }
        #pragma unroll
        for (int e = tid; e < 64 * 16; e += 256) {
            const int n = e >> 4, kq = e & 15;
            sB[n][kq] = W4[(size_t)(nbase + n) * 32 + kb * 16 + kq];
        }
        __syncthreads();

        #pragma unroll
        for (int kq = 0; kq < 16; kq++) {
            const float4 a0 = sA[ty * 4 + 0][kq];
            const float4 a1 = sA[ty * 4 + 1][kq];
            const float4 a2 = sA[ty * 4 + 2][kq];
            const float4 a3 = sA[ty * 4 + 3][kq];
            const float4 b0 = sB[tx * 4 + 0][kq];
            const float4 b1 = sB[tx * 4 + 1][kq];
            const float4 b2 = sB[tx * 4 + 2][kq];
            const float4 b3 = sB[tx * 4 + 3][kq];

            c00 += a0.x*b0.x + a0.y*b0.y + a0.z*b0.z + a0.w*b0.w;
            c01 += a0.x*b1.x + a0.y*b1.y + a0.z*b1.z + a0.w*b1.w;
            c02 += a0.x*b2.x + a0.y*b2.y + a0.z*b2.z + a0.w*b2.w;
            c03 += a0.x*b3.x + a0.y*b3.y + a0.z*b3.z + a0.w*b3.w;
            c10 += a1.x*b0.x + a1.y*b0.y + a1.z*b0.z + a1.w*b0.w;
            c11 += a1.x*b1.x + a1.y*b1.y + a1.z*b1.z + a1.w*b1.w;
            c12 += a1.x*b2.x + a1.y*b2.y + a1.z*b2.z + a1.w*b2.w;
            c13 += a1.x*b3.x + a1.y*b3.y + a1.z*b3.z + a1.w*b3.w;
            c20 += a2.x*b0.x + a2.y*b0.y + a2.z*b0.z + a2.w*b0.w;
            c21 += a2.x*b1.x + a2.y*b1.y + a2.z*b1.z + a2.w*b1.w;
            c22 += a2.x*b2.x + a2.y*b2.y + a2.z*b2.z + a2.w*b2.w;
            c23 += a2.x*b3.x + a2.y*b3.y + a2.z*b3.z + a2.w*b3.w;
            c30 += a3.x*b0.x + a3.y*b0.y + a3.z*b0.z + a3.w*b0.w;
            c31 += a3.x*b1.x + a3.y*b1.y + a3.z*b1.z + a3.w*b1.w;
            c32 += a3.x*b2.x + a3.y*b2.y + a3.z*b2.z + a3.w*b2.w;
            c33 += a3.x*b3.x + a3.y*b3.y + a3.z*b3.z + a3.w*b3.w;
        }
        __syncthreads();
    }

    const int m0 = mbase + ty * 4;
    const int n4 = nt * 16 + tx;
    C4[(size_t)(m0 + 0) * 96 + n4] = make_float4(c00, c01, c02, c03);
    C4[(size_t)(m0 + 1) * 96 + n4] = make_float4(c10, c11, c12, c13);
    C4[(size_t)(m0 + 2) * 96 + n4] = make_float4(c20, c21, c22, c23);
    C4[(size_t)(m0 + 3) * 96 + n4] = make_float4(c30, c31, c32, c33);
}

// ---------------------------------------------------------------------------
// Kernel 3: fused GRU epilogue. One thread per (i,h).
// ---------------------------------------------------------------------------
__global__ __launch_bounds__(256) void gru_ep_kernel(
    const float* __restrict__ nf,
    const float* __restrict__ bih,
    const float* __restrict__ bhh,
    float*       __restrict__ out)
{
    const int idx = blockIdx.x * 256 + threadIdx.x;   // i*128 + h
    const int i = idx >> 7;
    const int h = idx & 127;
    const size_t base = (size_t)i * 384 + h;

    const float r = 1.f / (1.f + __expf(-(g_gi[base] + g_gh[base]
                                          + bih[h] + bhh[h])));
    const float z = 1.f / (1.f + __expf(-(g_gi[base + 128] + g_gh[base + 128]
                                          + bih[h + 128] + bhh[h + 128])));
    const float n = tanhf(g_gi[base + 256] + bih[h + 256]
                          + r * (g_gh[base + 256] + bhh[h + 256]));
    out[idx] = (1.f - z) * n + z * nf[idx];
}

extern "C" void kernel_launch(void* const* d_in, const int* in_sizes, int n_in,
                              void* d_out, int out_size)
{
    const float* nf  = (const float*)d_in[0];
    const int*   adj = (const int*)  d_in[1];
    const float* T   = (const float*)d_in[2];
    const float* wih = (const float*)d_in[3];
    const float* whh = (const float*)d_in[4];
    const float* bih = (const float*)d_in[5];
    const float* bhh = (const float*)d_in[6];
    float* out = (float*)d_out;

    agg_kernel<<<dim3(NN / 8, NJB), 256>>>(nf, adj, T);
    gemm_kernel<<<dim3(16, 6, 2), 256>>>(nf, wih, whh);
    gru_ep_kernel<<<(NN * HH) / 256, 256>>>(nf, bih, bhh, out);
}